// round 2
// baseline (speedup 1.0000x reference)
#include <cuda_runtime.h>
#include <cstdint>

#define Tn 2048
#define KT 48
#define NEGV -10000.0f
#define START_T 46
#define END_T 47

// ---------------- device scratch (static, no allocation) ----------------
__device__ float g_xg[2][Tn][1024];   // per-layer gate preactivations, 2 dirs (16 MB)
__device__ float g_x1[Tn][512];       // layer-0 output / layer-1 input
__device__ float g_x2[Tn][512];       // layer-1 output
__device__ float g_feats[Tn][KT];
__device__ float g_wT[512][KT];       // W_out transposed

// ---------------- gates GEMM: C[dir][m][n] = A[m] . W[n] + bi[n]+bh[n] ----------------
__global__ __launch_bounds__(256) void gates_gemm(
    const int* __restrict__ sent, const float* __restrict__ emb,
    const float* __restrict__ W, const float* __restrict__ bi,
    const float* __restrict__ bh, int layer)
{
    const int dir = blockIdx.z;
    W  += (size_t)dir * 1024 * 512;
    bi += dir * 1024;
    bh += dir * 1024;

    const int n0 = blockIdx.x * 64;
    const int m0 = blockIdx.y * 64;

    __shared__ __align__(16) float As[16][64];
    __shared__ __align__(16) float Bs[16][64];

    const int tid = threadIdx.x;
    const int tx = tid & 15;
    const int ty = tid >> 4;

    const int lr = tid >> 2;          // 0..63 row in tile
    const int lk = (tid & 3) * 4;     // 0,4,8,12 k in tile

    const int mrow = m0 + lr;
    const int sr = dir ? (Tn - 1 - mrow) : mrow;
    const float* arow;
    if (layer == 0) arow = emb + (size_t)sent[sr] * 512;
    else            arow = &g_x1[sr][0];
    const float* brow = W + (size_t)(n0 + lr) * 512;

    float acc[4][4] = {};

    for (int k0 = 0; k0 < 512; k0 += 16) {
        float4 av = *(const float4*)(arow + k0 + lk);
        float4 bv = *(const float4*)(brow + k0 + lk);
        __syncthreads();
        As[lk + 0][lr] = av.x; As[lk + 1][lr] = av.y;
        As[lk + 2][lr] = av.z; As[lk + 3][lr] = av.w;
        Bs[lk + 0][lr] = bv.x; Bs[lk + 1][lr] = bv.y;
        Bs[lk + 2][lr] = bv.z; Bs[lk + 3][lr] = bv.w;
        __syncthreads();
        #pragma unroll
        for (int k = 0; k < 16; k++) {
            float4 a = *(const float4*)&As[k][ty * 4];
            float4 b = *(const float4*)&Bs[k][tx * 4];
            float am[4] = {a.x, a.y, a.z, a.w};
            float bm[4] = {b.x, b.y, b.z, b.w};
            #pragma unroll
            for (int i = 0; i < 4; i++)
                #pragma unroll
                for (int j = 0; j < 4; j++)
                    acc[i][j] += am[i] * bm[j];
        }
    }
    #pragma unroll
    for (int i = 0; i < 4; i++) {
        int m = m0 + ty * 4 + i;
        #pragma unroll
        for (int j = 0; j < 4; j++) {
            int n = n0 + tx * 4 + j;
            g_xg[dir][m][n] = acc[i][j] + bi[n] + bh[n];
        }
    }
}

// ---------------- fast activations (fp32, ~1e-7 rel err) ----------------
__device__ __forceinline__ float sigf(float x) {
    return __fdividef(1.0f, 1.0f + __expf(-x));
}
__device__ __forceinline__ float tanh_fast(float x) {
    float e = __expf(-2.0f * x);
    return __fdividef(1.0f - e, 1.0f + e);
}

// wait with acquire at cluster scope
__device__ __forceinline__ void mbar_wait_cluster(uint32_t mb, uint32_t parity) {
    uint32_t done;
    asm volatile(
        "{\n\t.reg .pred P;\n\t"
        "mbarrier.try_wait.parity.acquire.cluster.shared::cta.b64 P, [%1], %2;\n\t"
        "selp.b32 %0, 1, 0, P;\n\t}"
        : "=r"(done) : "r"(mb), "r"(parity) : "memory");
    while (!done) {
        asm volatile(
            "{\n\t.reg .pred P;\n\t"
            "mbarrier.try_wait.parity.acquire.cluster.shared::cta.b64 P, [%1], %2, 0x989680;\n\t"
            "selp.b32 %0, 1, 0, P;\n\t}"
            : "=r"(done) : "r"(mb), "r"(parity) : "memory");
    }
}

// ---------------- LSTM recurrence: cluster of 8 CTAs per direction ----------------
// lane layout within a warp: bit4 = jj (local output pair idx), bits3:2 = gate, bits1:0 = kq
__global__ void __cluster_dims__(8, 1, 1) __launch_bounds__(512, 1)
lstm_rec(const float* __restrict__ whh, int layer)
{
    const int dir  = blockIdx.x >> 3;
    const int rank = blockIdx.x & 7;
    whh += (size_t)dir * 1024 * 256;
    const float* xg = &g_xg[dir][0][0];

    const int tid  = threadIdx.x;
    const int wrp  = tid >> 5;
    const int lane = tid & 31;
    const int jj   = lane >> 4;
    const int kq   = lane & 3;
    const int jloc = wrp * 2 + jj;                          // 0..31 local output
    const int gate = (lane >> 2) & 3;                       // 0..3 (i,f,g,o)
    const int row  = gate * 256 + rank * 32 + jloc;         // global whh row

    // 64 weights / thread, packed f32x2 in 32 u64 regs
    unsigned long long w[32];
    {
        const ulonglong2* wp = (const ulonglong2*)(whh + (size_t)row * 256 + kq * 64);
        #pragma unroll
        for (int i = 0; i < 16; ++i) {
            ulonglong2 v = wp[i];
            w[2 * i] = v.x; w[2 * i + 1] = v.y;
        }
    }

    __shared__ __align__(16) float hbuf[2][256];
    __shared__ __align__(8) unsigned long long mbar[2];

    if (tid < 256) hbuf[0][tid] = 0.0f;
    const uint32_t hb_local = (uint32_t)__cvta_generic_to_shared(&hbuf[0][0]);
    const uint32_t mb_local = (uint32_t)__cvta_generic_to_shared(&mbar[0]);
    if (tid == 0) {
        asm volatile("mbarrier.init.shared.b64 [%0], %1;" :: "r"(mb_local), "r"(256u));
        asm volatile("mbarrier.init.shared.b64 [%0], %1;" :: "r"(mb_local + 8), "r"(256u));
    }
    __syncthreads();
    asm volatile("barrier.cluster.arrive.aligned;" ::: "memory");
    asm volatile("barrier.cluster.wait.aligned;"   ::: "memory");

    // remote hbuf bases for all 8 CTAs; mbar derived by constant delta
    uint32_t r_hb[8];
    const uint32_t mb_delta = mb_local - hb_local;
    #pragma unroll
    for (int tc = 0; tc < 8; ++tc)
        asm("mapa.shared::cluster.u32 %0, %1, %2;" : "=r"(r_hb[tc]) : "r"(hb_local), "r"(tc));

    float c = 0.0f;
    float xgv = __ldg(xg + row);
    uint32_t ph0 = 0, ph1 = 0;
    float* xo = layer ? &g_x2[0][0] : &g_x1[0][0];

    for (int s = 0; s < Tn; ++s) {
        // prefetch next step's xg early (independent of h)
        int sn = (s + 1 < Tn) ? s + 1 : s;
        float xgn = __ldg(xg + (size_t)sn * 1024 + row);

        if (s) {
            int b = s & 1;
            mbar_wait_cluster(mb_local + b * 8, b ? ph1 : ph0);
            if (b) ph1 ^= 1; else ph0 ^= 1;
        }

        // matvec: 32 packed f32x2 FMAs over h slice [kq*64, kq*64+64)
        unsigned long long a0 = 0ull, a1 = 0ull, a2 = 0ull, a3 = 0ull;
        const ulonglong2* hp = (const ulonglong2*)(&hbuf[s & 1][kq * 64]);
        #pragma unroll
        for (int i = 0; i < 8; ++i) {
            ulonglong2 h01 = hp[2 * i];
            ulonglong2 h23 = hp[2 * i + 1];
            asm("fma.rn.f32x2 %0, %1, %2, %0;" : "+l"(a0) : "l"(w[4 * i + 0]), "l"(h01.x));
            asm("fma.rn.f32x2 %0, %1, %2, %0;" : "+l"(a1) : "l"(w[4 * i + 1]), "l"(h01.y));
            asm("fma.rn.f32x2 %0, %1, %2, %0;" : "+l"(a2) : "l"(w[4 * i + 2]), "l"(h23.x));
            asm("fma.rn.f32x2 %0, %1, %2, %0;" : "+l"(a3) : "l"(w[4 * i + 3]), "l"(h23.y));
        }
        // all reads of hbuf[s&1] by this CTA are done once every warp passes here;
        // the arrives below therefore certify the old buffer is reusable.
        __syncthreads();

        unsigned long long t01, t23, tt;
        asm("add.rn.f32x2 %0, %1, %2;" : "=l"(t01) : "l"(a0), "l"(a1));
        asm("add.rn.f32x2 %0, %1, %2;" : "=l"(t23) : "l"(a2), "l"(a3));
        asm("add.rn.f32x2 %0, %1, %2;" : "=l"(tt)  : "l"(t01), "l"(t23));
        float acc = __uint_as_float((uint32_t)tt) + __uint_as_float((uint32_t)(tt >> 32));

        // reduce over kq (bits 0-1): butterfly -> all 4 lanes hold the row sum
        acc += __shfl_xor_sync(0xffffffffu, acc, 1);
        acc += __shfl_xor_sync(0xffffffffu, acc, 2);
        float g = acc + xgv;
        xgv = xgn;

        // gather the 4 gates of output jj from lanes base|{0,4,8,12}
        int base = lane & 19;  // zero gate bits
        float gi = __shfl_sync(0xffffffffu, g, base);
        float gf = __shfl_sync(0xffffffffu, g, base | 4);
        float gg = __shfl_sync(0xffffffffu, g, base | 8);
        float go = __shfl_sync(0xffffffffu, g, base | 12);

        // all lanes compute identical (c, hn) for their jj — redundant but divergence-free
        c = sigf(gf) * c + sigf(gi) * tanh_fast(gg);
        float hn = sigf(go) * tanh_fast(c);

        if ((lane & 15) == 0) {
            int t = dir ? (Tn - 1 - s) : s;
            xo[(size_t)t * 512 + dir * 256 + rank * 32 + jloc] = hn;
            if (s + 1 < Tn) {
                uint32_t boff = (uint32_t)((((s + 1) & 1) * 256 + rank * 32 + jloc) * 4);
                uint32_t moff = mb_delta + ((s + 1) & 1) * 8;
                #pragma unroll
                for (int tc = 0; tc < 8; ++tc) {
                    asm volatile("st.shared::cluster.f32 [%0], %1;"
                                 :: "r"(r_hb[tc] + boff), "f"(hn) : "memory");
                    asm volatile("mbarrier.arrive.release.cluster.shared::cluster.b64 _, [%0];"
                                 :: "r"(r_hb[tc] + moff) : "memory");
                }
            }
        }
    }
    asm volatile("barrier.cluster.arrive.aligned;" ::: "memory");
    asm volatile("barrier.cluster.wait.aligned;"   ::: "memory");
}

// ---------------- W_out transpose ----------------
__global__ void wout_transpose(const float* __restrict__ W)
{
    int idx = blockIdx.x * 256 + threadIdx.x;     // 48*512
    if (idx < KT * 512) {
        int j = idx / 512, k = idx % 512;
        g_wT[k][j] = W[idx];
    }
}

// ---------------- feats = x2 @ W_out^T + b_out ----------------
__global__ __launch_bounds__(64) void feats_kernel(const float* __restrict__ bout)
{
    int row = blockIdx.x;
    __shared__ __align__(16) float xs[512];
    int tid = threadIdx.x;
    #pragma unroll
    for (int i = 0; i < 2; i++)
        ((float4*)xs)[tid * 2 + i] = ((const float4*)&g_x2[row][0])[tid * 2 + i];
    __syncthreads();
    if (tid < KT) {
        float a0 = 0.f, a1 = 0.f, a2 = 0.f, a3 = 0.f;
        #pragma unroll 4
        for (int k = 0; k < 512; k += 4) {
            a0 += xs[k + 0] * g_wT[k + 0][tid];
            a1 += xs[k + 1] * g_wT[k + 1][tid];
            a2 += xs[k + 2] * g_wT[k + 2][tid];
            a3 += xs[k + 3] * g_wT[k + 3][tid];
        }
        g_feats[row][tid] = (a0 + a1) + (a2 + a3) + bout[tid];
    }
}

// ---------------- Viterbi (single CTA, backpointers in smem) ----------------
__global__ __launch_bounds__(64) void viterbi(const float* __restrict__ trans,
                                              float* __restrict__ out, int out_size)
{
    extern __shared__ unsigned char sm[];
    unsigned char* bp = sm;                       // Tn*KT bytes
    float* fv = (float*)(sm + Tn * KT);           // 2*KT ping-pong
    const int j = threadIdx.x;

    float tr[KT];
    if (j < KT) {
        #pragma unroll
        for (int p = 0; p < KT; p++) tr[p] = trans[j * KT + p];
        fv[j] = (j == START_T) ? 0.0f : NEGV;
    }
    __syncthreads();

    for (int t = 0; t < Tn; ++t) {
        const float* fcur = fv + (t & 1) * KT;
        float* fnxt = fv + ((t + 1) & 1) * KT;
        if (j < KT) {
            float best = -3.4e38f; int arg = 0;
            #pragma unroll
            for (int p = 0; p < KT; p++) {
                float s = fcur[p] + tr[p];
                if (s > best) { best = s; arg = p; }   // first max, matches jnp.argmax
            }
            fnxt[j] = best + g_feats[t][j];
            bp[t * KT + j] = (unsigned char)arg;
        }
        __syncthreads();
    }

    __shared__ float term[KT];
    if (j < KT) term[j] = fv[(Tn & 1) * KT + j] + trans[END_T * KT + j];
    __syncthreads();

    if (j == 0) {
        float best = -3.4e38f; int arg = 0;
        for (int p = 0; p < KT; p++)
            if (term[p] > best) { best = term[p]; arg = p; }

        int off = 0;
        if (out_size >= Tn + 1) { out[0] = best; off = 1; }
        else if (out_size == 1) { out[0] = best; }
        if (out_size >= Tn) {
            int cur = arg;
            for (int t = Tn - 1; t >= 0; --t) {
                out[off + t] = (float)cur;
                cur = bp[t * KT + cur];
            }
        }
    }
}

// ---------------- launch ----------------
extern "C" void kernel_launch(void* const* d_in, const int* in_sizes, int n_in,
                              void* d_out, int out_size)
{
    const int*   sent  = (const int*)  d_in[0];
    const float* emb   = (const float*)d_in[1];
    const float* wih   = (const float*)d_in[2];
    const float* whh   = (const float*)d_in[3];
    const float* bih   = (const float*)d_in[4];
    const float* bhh   = (const float*)d_in[5];
    const float* wout  = (const float*)d_in[6];
    const float* bout  = (const float*)d_in[7];
    const float* trans = (const float*)d_in[8];
    float* out = (float*)d_out;

    const int vit_smem = Tn * KT + 2 * KT * 4 + 16;
    cudaFuncSetAttribute(viterbi, cudaFuncAttributeMaxDynamicSharedMemorySize, vit_smem);

    dim3 ggrid(16, 32, 2);   // N/64, M/64, dirs

    // layer 0
    gates_gemm<<<ggrid, 256>>>(sent, emb, wih, bih, bhh, 0);
    lstm_rec<<<16, 512>>>(whh, 0);
    // layer 1
    gates_gemm<<<ggrid, 256>>>(sent, emb, wih + 2 * 1024 * 512, bih + 2 * 1024, bhh + 2 * 1024, 1);
    lstm_rec<<<16, 512>>>(whh + 2 * 1024 * 256, 1);
    // output projection + viterbi
    wout_transpose<<<96, 256>>>(wout);
    feats_kernel<<<Tn, 64>>>(bout);
    viterbi<<<1, 64, vit_smem>>>(trans, out, out_size);
}

// round 3
// speedup vs baseline: 1.8440x; 1.8440x over previous
#include <cuda_runtime.h>
#include <cstdint>

#define Tn 2048
#define KT 48
#define NEGV -10000.0f
#define START_T 46
#define END_T 47

// ---------------- device scratch (static, no allocation) ----------------
__device__ float g_xg[2][Tn][1024];   // per-layer gate preactivations, 2 dirs (16 MB)
__device__ float g_x1[Tn][512];       // layer-0 output / layer-1 input
__device__ float g_x2[Tn][512];       // layer-1 output
__device__ float g_feats[Tn][KT];
__device__ float g_wT[512][KT];       // W_out transposed

// ---------------- gates GEMM: C[dir][m][n] = A[m] . W[n] + bi[n]+bh[n] ----------------
__global__ __launch_bounds__(256) void gates_gemm(
    const int* __restrict__ sent, const float* __restrict__ emb,
    const float* __restrict__ W, const float* __restrict__ bi,
    const float* __restrict__ bh, int layer)
{
    const int dir = blockIdx.z;
    W  += (size_t)dir * 1024 * 512;
    bi += dir * 1024;
    bh += dir * 1024;

    const int n0 = blockIdx.x * 64;
    const int m0 = blockIdx.y * 64;

    __shared__ __align__(16) float As[16][64];
    __shared__ __align__(16) float Bs[16][64];

    const int tid = threadIdx.x;
    const int tx = tid & 15;
    const int ty = tid >> 4;

    const int lr = tid >> 2;          // 0..63 row in tile
    const int lk = (tid & 3) * 4;     // 0,4,8,12 k in tile

    const int mrow = m0 + lr;
    const int sr = dir ? (Tn - 1 - mrow) : mrow;
    const float* arow;
    if (layer == 0) arow = emb + (size_t)sent[sr] * 512;
    else            arow = &g_x1[sr][0];
    const float* brow = W + (size_t)(n0 + lr) * 512;

    float acc[4][4] = {};

    for (int k0 = 0; k0 < 512; k0 += 16) {
        float4 av = *(const float4*)(arow + k0 + lk);
        float4 bv = *(const float4*)(brow + k0 + lk);
        __syncthreads();
        As[lk + 0][lr] = av.x; As[lk + 1][lr] = av.y;
        As[lk + 2][lr] = av.z; As[lk + 3][lr] = av.w;
        Bs[lk + 0][lr] = bv.x; Bs[lk + 1][lr] = bv.y;
        Bs[lk + 2][lr] = bv.z; Bs[lk + 3][lr] = bv.w;
        __syncthreads();
        #pragma unroll
        for (int k = 0; k < 16; k++) {
            float4 a = *(const float4*)&As[k][ty * 4];
            float4 b = *(const float4*)&Bs[k][tx * 4];
            float am[4] = {a.x, a.y, a.z, a.w};
            float bm[4] = {b.x, b.y, b.z, b.w};
            #pragma unroll
            for (int i = 0; i < 4; i++)
                #pragma unroll
                for (int j = 0; j < 4; j++)
                    acc[i][j] += am[i] * bm[j];
        }
    }
    #pragma unroll
    for (int i = 0; i < 4; i++) {
        int m = m0 + ty * 4 + i;
        #pragma unroll
        for (int j = 0; j < 4; j++) {
            int n = n0 + tx * 4 + j;
            g_xg[dir][m][n] = acc[i][j] + bi[n] + bh[n];
        }
    }
}

// ---------------- fast activations (fp32, ~1e-7 rel err) ----------------
__device__ __forceinline__ float sigf(float x) {
    return __fdividef(1.0f, 1.0f + __expf(-x));
}
__device__ __forceinline__ float tanh_fast(float x) {
    float e = __expf(-2.0f * x);
    return __fdividef(1.0f - e, 1.0f + e);
}

// acquire wait at cluster scope (data written by peer CTAs via st.async)
__device__ __forceinline__ void mbar_wait_cluster(uint32_t mb, uint32_t parity) {
    uint32_t done;
    asm volatile(
        "{\n\t.reg .pred P;\n\t"
        "mbarrier.try_wait.parity.acquire.cluster.shared::cta.b64 P, [%1], %2;\n\t"
        "selp.b32 %0, 1, 0, P;\n\t}"
        : "=r"(done) : "r"(mb), "r"(parity) : "memory");
    while (!done) {
        asm volatile(
            "{\n\t.reg .pred P;\n\t"
            "mbarrier.try_wait.parity.acquire.cluster.shared::cta.b64 P, [%1], %2, 0x989680;\n\t"
            "selp.b32 %0, 1, 0, P;\n\t}"
            : "=r"(done) : "r"(mb), "r"(parity) : "memory");
    }
}

// ---------------- LSTM recurrence: cluster of 8 CTAs per direction ----------------
// 4-deep buffer/barrier ring; producers push h via st.async with HW tx completion.
// lane layout: bit4 = jj (local output), bits3:2 = gate, bits1:0 = kq
__global__ void __cluster_dims__(8, 1, 1) __launch_bounds__(512, 1)
lstm_rec(const float* __restrict__ whh, int layer)
{
    const int dir  = blockIdx.x >> 3;
    const int rank = blockIdx.x & 7;
    whh += (size_t)dir * 1024 * 256;
    const float* xg = &g_xg[dir][0][0];

    const int tid  = threadIdx.x;
    const int wrp  = tid >> 5;
    const int lane = tid & 31;
    const int jj   = lane >> 4;
    const int kq   = lane & 3;
    const int jloc = wrp * 2 + jj;                          // 0..31 local output
    const int gate = (lane >> 2) & 3;                       // i,f,g,o
    const int row  = gate * 256 + rank * 32 + jloc;         // global whh row

    // 64 weights / thread, packed f32x2 in 32 u64 regs
    unsigned long long w[32];
    {
        const ulonglong2* wp = (const ulonglong2*)(whh + (size_t)row * 256 + kq * 64);
        #pragma unroll
        for (int i = 0; i < 16; ++i) {
            ulonglong2 v = wp[i];
            w[2 * i] = v.x; w[2 * i + 1] = v.y;
        }
    }

    __shared__ __align__(16) float hbuf[4][256];
    __shared__ __align__(8) unsigned long long mbar[4];

    if (tid < 256) hbuf[0][tid] = 0.0f;
    const uint32_t hb_local = (uint32_t)__cvta_generic_to_shared(&hbuf[0][0]);
    const uint32_t mb_local = (uint32_t)__cvta_generic_to_shared(&mbar[0]);
    if (tid == 0) {
        #pragma unroll
        for (int b = 0; b < 4; ++b) {
            asm volatile("mbarrier.init.shared.b64 [%0], %1;"
                         :: "r"(mb_local + b * 8), "r"(1u));
        }
        // fence so peers' st.async (async proxy) observe initialized barriers
        asm volatile("fence.proxy.async.shared::cta;" ::: "memory");
        // pre-arm all 4 barriers for their first use (1024 B = 8 CTAs x 32 floats)
        #pragma unroll
        for (int b = 0; b < 4; ++b) {
            asm volatile("mbarrier.arrive.expect_tx.shared::cta.b64 _, [%0], %1;"
                         :: "r"(mb_local + b * 8), "r"(1024u) : "memory");
        }
    }
    __syncthreads();
    asm volatile("barrier.cluster.arrive.aligned;" ::: "memory");
    asm volatile("barrier.cluster.wait.aligned;"   ::: "memory");

    // remote smem bases for all 8 CTAs (mbar at constant delta from hbuf)
    uint32_t r_hb[8];
    const uint32_t mb_delta = mb_local - hb_local;
    #pragma unroll
    for (int tc = 0; tc < 8; ++tc)
        asm("mapa.shared::cluster.u32 %0, %1, %2;" : "=r"(r_hb[tc]) : "r"(hb_local), "r"(tc));

    float c = 0.0f;
    float xgv = __ldg(xg + row);
    float* xo = layer ? &g_x2[0][0] : &g_x1[0][0];

    for (int s = 0; s < Tn; ++s) {
        // prefetch next step's xg (independent of h)
        int sn = (s + 1 < Tn) ? s + 1 : s;
        float xgn = __ldg(xg + (size_t)sn * 1024 + row);

        if (s) {
            const int b = s & 3;
            const uint32_t par = (uint32_t)(((s >> 2) - (b == 0 ? 1 : 0)) & 1);
            mbar_wait_cluster(mb_local + b * 8, par);
            if (tid == 0) {  // re-arm for use at step s+4
                asm volatile("mbarrier.arrive.expect_tx.shared::cta.b64 _, [%0], %1;"
                             :: "r"(mb_local + b * 8), "r"(1024u) : "memory");
            }
        }

        // matvec: 32 packed f32x2 FMAs over h slice [kq*64, kq*64+64)
        unsigned long long a0 = 0ull, a1 = 0ull, a2 = 0ull, a3 = 0ull;
        const ulonglong2* hp = (const ulonglong2*)(&hbuf[s & 3][kq * 64]);
        #pragma unroll
        for (int i = 0; i < 8; ++i) {
            ulonglong2 h01 = hp[2 * i];
            ulonglong2 h23 = hp[2 * i + 1];
            asm("fma.rn.f32x2 %0, %1, %2, %0;" : "+l"(a0) : "l"(w[4 * i + 0]), "l"(h01.x));
            asm("fma.rn.f32x2 %0, %1, %2, %0;" : "+l"(a1) : "l"(w[4 * i + 1]), "l"(h01.y));
            asm("fma.rn.f32x2 %0, %1, %2, %0;" : "+l"(a2) : "l"(w[4 * i + 2]), "l"(h23.x));
            asm("fma.rn.f32x2 %0, %1, %2, %0;" : "+l"(a3) : "l"(w[4 * i + 3]), "l"(h23.y));
        }
        unsigned long long t01, t23, tt;
        asm("add.rn.f32x2 %0, %1, %2;" : "=l"(t01) : "l"(a0), "l"(a1));
        asm("add.rn.f32x2 %0, %1, %2;" : "=l"(t23) : "l"(a2), "l"(a3));
        asm("add.rn.f32x2 %0, %1, %2;" : "=l"(tt)  : "l"(t01), "l"(t23));
        float acc = __uint_as_float((uint32_t)tt) + __uint_as_float((uint32_t)(tt >> 32));

        // reduce over kq: butterfly -> all 4 lanes hold the row sum
        acc += __shfl_xor_sync(0xffffffffu, acc, 1);
        acc += __shfl_xor_sync(0xffffffffu, acc, 2);
        float g = acc + xgv;
        xgv = xgn;

        // gather the 4 gates of output jj from lanes base|{0,4,8,12}
        int base = lane & 19;  // clear gate bits
        float gi = __shfl_sync(0xffffffffu, g, base);
        float gf = __shfl_sync(0xffffffffu, g, base | 4);
        float gg = __shfl_sync(0xffffffffu, g, base | 8);
        float go = __shfl_sync(0xffffffffu, g, base | 12);

        c = sigf(gf) * c + sigf(gi) * tanh_fast(gg);
        float hn = sigf(go) * tanh_fast(c);

        if ((lane & 15) == 0) {
            int t = dir ? (Tn - 1 - s) : s;
            xo[(size_t)t * 512 + dir * 256 + rank * 32 + jloc] = hn;
            if (s + 1 < Tn) {
                const uint32_t boff = (uint32_t)((((s + 1) & 3) * 256 + rank * 32 + jloc) * 4);
                const uint32_t moff = mb_delta + ((s + 1) & 3) * 8;
                const uint32_t hv = __float_as_uint(hn);
                #pragma unroll
                for (int tc = 0; tc < 8; ++tc) {
                    // fire-and-forget store with HW tx completion on the peer's barrier
                    asm volatile(
                        "st.async.shared::cluster.mbarrier::complete_tx::bytes.b32 [%0], %1, [%2];"
                        :: "r"(r_hb[tc] + boff), "r"(hv), "r"(r_hb[tc] + moff) : "memory");
                }
            }
        }
    }
    asm volatile("barrier.cluster.arrive.aligned;" ::: "memory");
    asm volatile("barrier.cluster.wait.aligned;"   ::: "memory");
}

// ---------------- W_out transpose ----------------
__global__ void wout_transpose(const float* __restrict__ W)
{
    int idx = blockIdx.x * 256 + threadIdx.x;     // 48*512
    if (idx < KT * 512) {
        int j = idx / 512, k = idx % 512;
        g_wT[k][j] = W[idx];
    }
}

// ---------------- feats = x2 @ W_out^T + b_out ----------------
__global__ __launch_bounds__(64) void feats_kernel(const float* __restrict__ bout)
{
    int row = blockIdx.x;
    __shared__ __align__(16) float xs[512];
    int tid = threadIdx.x;
    #pragma unroll
    for (int i = 0; i < 2; i++)
        ((float4*)xs)[tid * 2 + i] = ((const float4*)&g_x2[row][0])[tid * 2 + i];
    __syncthreads();
    if (tid < KT) {
        float a0 = 0.f, a1 = 0.f, a2 = 0.f, a3 = 0.f;
        #pragma unroll 4
        for (int k = 0; k < 512; k += 4) {
            a0 += xs[k + 0] * g_wT[k + 0][tid];
            a1 += xs[k + 1] * g_wT[k + 1][tid];
            a2 += xs[k + 2] * g_wT[k + 2][tid];
            a3 += xs[k + 3] * g_wT[k + 3][tid];
        }
        g_feats[row][tid] = (a0 + a1) + (a2 + a3) + bout[tid];
    }
}

// ---------------- Viterbi (single CTA, backpointers in smem) ----------------
__global__ __launch_bounds__(64) void viterbi(const float* __restrict__ trans,
                                              float* __restrict__ out, int out_size)
{
    extern __shared__ unsigned char sm[];
    unsigned char* bp = sm;                       // Tn*KT bytes
    float* fv = (float*)(sm + Tn * KT);           // 2*KT ping-pong
    const int j = threadIdx.x;

    float tr[KT];
    if (j < KT) {
        #pragma unroll
        for (int p = 0; p < KT; p++) tr[p] = trans[j * KT + p];
        fv[j] = (j == START_T) ? 0.0f : NEGV;
    }
    __syncthreads();

    for (int t = 0; t < Tn; ++t) {
        const float* fcur = fv + (t & 1) * KT;
        float* fnxt = fv + ((t + 1) & 1) * KT;
        if (j < KT) {
            float best = -3.4e38f; int arg = 0;
            #pragma unroll
            for (int p = 0; p < KT; p++) {
                float s = fcur[p] + tr[p];
                if (s > best) { best = s; arg = p; }   // first max, matches jnp.argmax
            }
            fnxt[j] = best + g_feats[t][j];
            bp[t * KT + j] = (unsigned char)arg;
        }
        __syncthreads();
    }

    __shared__ float term[KT];
    if (j < KT) term[j] = fv[(Tn & 1) * KT + j] + trans[END_T * KT + j];
    __syncthreads();

    if (j == 0) {
        float best = -3.4e38f; int arg = 0;
        for (int p = 0; p < KT; p++)
            if (term[p] > best) { best = term[p]; arg = p; }

        int off = 0;
        if (out_size >= Tn + 1) { out[0] = best; off = 1; }
        else if (out_size == 1) { out[0] = best; }
        if (out_size >= Tn) {
            int cur = arg;
            for (int t = Tn - 1; t >= 0; --t) {
                out[off + t] = (float)cur;
                cur = bp[t * KT + cur];
            }
        }
    }
}

// ---------------- launch ----------------
extern "C" void kernel_launch(void* const* d_in, const int* in_sizes, int n_in,
                              void* d_out, int out_size)
{
    const int*   sent  = (const int*)  d_in[0];
    const float* emb   = (const float*)d_in[1];
    const float* wih   = (const float*)d_in[2];
    const float* whh   = (const float*)d_in[3];
    const float* bih   = (const float*)d_in[4];
    const float* bhh   = (const float*)d_in[5];
    const float* wout  = (const float*)d_in[6];
    const float* bout  = (const float*)d_in[7];
    const float* trans = (const float*)d_in[8];
    float* out = (float*)d_out;

    const int vit_smem = Tn * KT + 2 * KT * 4 + 16;
    cudaFuncSetAttribute(viterbi, cudaFuncAttributeMaxDynamicSharedMemorySize, vit_smem);

    dim3 ggrid(16, 32, 2);   // N/64, M/64, dirs

    // layer 0
    gates_gemm<<<ggrid, 256>>>(sent, emb, wih, bih, bhh, 0);
    lstm_rec<<<16, 512>>>(whh, 0);
    // layer 1
    gates_gemm<<<ggrid, 256>>>(sent, emb, wih + 2 * 1024 * 512, bih + 2 * 1024, bhh + 2 * 1024, 1);
    lstm_rec<<<16, 512>>>(whh + 2 * 1024 * 256, 1);
    // output projection + viterbi
    wout_transpose<<<96, 256>>>(wout);
    feats_kernel<<<Tn, 64>>>(bout);
    viterbi<<<1, 64, vit_smem>>>(trans, out, out_size);
}